// round 15
// baseline (speedup 1.0000x reference)
#include <cuda_runtime.h>
#include <cstdint>

#define Nn   100000
#define Ee   1000000
#define FIN  128
#define HID  64
#define OUTF 40
#define NL   4
#define ALPHAc 0.5f
#define EPSBN  1e-5f

#define NB_SCAN ((Nn + 255) / 256)   // 391
#define NTILE   ((Nn + 127) / 128)   // 782

// ---------------- scratch ----------------------------------------------------
__device__ __align__(16) float g_h0[Nn * HID];
__device__ __align__(16) float g_hprev[Nn * HID];
__device__ __align__(16) float g_support[Nn * HID];
__device__ __align__(16) float g_agg[Nn * HID];
__device__ __align__(16) float g_init[NL][Nn * HID];
__device__ float g_dinv[Nn];
__device__ float g_stats[2][2 * HID];
__device__ int   g_cnt[Nn];
__device__ int   g_bsum[NB_SCAN];
__device__ int   g_boff[NB_SCAN];
__device__ int   g_rowptr[Nn + 1];
__device__ int   g_cur[Nn];
__device__ __align__(8) int2 g_eidx[Ee];

// ---------------- edge index dtype handling -----------------------------------
__device__ __forceinline__ int detect64(const void* ei) {
    const long long* p = (const long long*)ei;
    int ok = 1;
    #pragma unroll
    for (int j = 0; j < 8; j++) {
        long long v = p[j];
        if (v < 0 || v >= Nn) ok = 0;
    }
    return ok;
}
__device__ __forceinline__ int edge_at(const void* ei, int is64, int idx) {
    if (is64) return (int)((const long long*)ei)[idx];
    return ((const int*)ei)[idx];
}

// ---------------- CSR build ----------------------------------------------------
__global__ void k_deg(const void* ei) {
    __shared__ int s64;
    if (threadIdx.x == 0) s64 = detect64(ei);
    __syncthreads();
    int e = blockIdx.x * blockDim.x + threadIdx.x;
    if (e < Ee) {
        int c = edge_at(ei, s64, Ee + e);
        atomicAdd(&g_cnt[c], 1);
    }
}

__global__ void k_bsum() {
    __shared__ int s[256];
    int t = threadIdx.x;
    int i = blockIdx.x * 256 + t;
    s[t] = (i < Nn) ? g_cnt[i] : 0;
    __syncthreads();
    for (int st = 128; st > 0; st >>= 1) {
        if (t < st) s[t] += s[t + st];
        __syncthreads();
    }
    if (t == 0) g_bsum[blockIdx.x] = s[0];
}

__global__ void k_bscan() {
    __shared__ int s[512];
    int t = threadIdx.x;
    int orig = (t < NB_SCAN) ? g_bsum[t] : 0;
    s[t] = orig;
    __syncthreads();
    for (int off = 1; off < 512; off <<= 1) {
        int v = (t >= off) ? s[t - off] : 0;
        __syncthreads();
        s[t] += v;
        __syncthreads();
    }
    if (t < NB_SCAN) g_boff[t] = s[t] - orig;
}

__global__ void k_rowptr() {
    __shared__ int s[256];
    int t = threadIdx.x;
    int i = blockIdx.x * 256 + t;
    int orig = (i < Nn) ? g_cnt[i] : 0;
    s[t] = orig;
    __syncthreads();
    for (int off = 1; off < 256; off <<= 1) {
        int v = (t >= off) ? s[t - off] : 0;
        __syncthreads();
        s[t] += v;
        __syncthreads();
    }
    if (i < Nn) {
        int rp = g_boff[blockIdx.x] + s[t] - orig;
        g_rowptr[i] = rp;
        g_cur[i] = rp;
        g_dinv[i] = rsqrtf((float)orig + 1.0f);
    }
    if (i == 0) g_rowptr[Nn] = Ee;
}

__global__ void k_fill(const void* __restrict__ ei) {
    __shared__ int s64;
    if (threadIdx.x == 0) s64 = detect64(ei);
    __syncthreads();
    int e = blockIdx.x * blockDim.x + threadIdx.x;
    if (e < Ee) {
        int r = edge_at(ei, s64, e);
        int c = edge_at(ei, s64, Ee + e);
        float w = g_dinv[r] * g_dinv[c];
        int pos = atomicAdd(&g_cur[c], 1);
        g_eidx[pos] = make_int2(r * HID, __float_as_int(w));
    }
}

// ---- fused prologue: h0 = relu(x@Wi+bi); support0 = h0@(I+W1); init0 = h0@(aI+W2)
#define FUSED_SMEM (64 * 132 * 4 + 128 * 64 * 4 + 64 * 4)
__global__ __launch_bounds__(256) void k_fused0(const float* __restrict__ x,
                                                const float* __restrict__ Wi,
                                                const float* __restrict__ bi,
                                                const float* __restrict__ W1,
                                                const float* __restrict__ W2,
                                                float* __restrict__ init0) {
    extern __shared__ float sm[];
    float* xs = sm;              // [64][132]
    float* wk = sm + 64 * 132;   // phase A: Wi [128][64]; phase B: W1 | W2
    float* bs = wk + 128 * 64;
    int tid = threadIdx.x;
    int rowBase = blockIdx.x * 128;
    for (int i = tid; i < 128 * 16; i += 256)
        *(float4*)(wk + i * 4) = *(const float4*)(Wi + i * 4);
    if (tid < HID) bs[tid] = bi[tid];
    __syncthreads();

    int rg = tid >> 3, cg = tid & 7;
    int r0 = rg * 4, f0 = cg * 4;
    float acc[4][8];
    #pragma unroll
    for (int i = 0; i < 4; i++)
        #pragma unroll
        for (int j = 0; j < 8; j++) acc[i][j] = 0.0f;

    for (int h = 0; h < 2; h++) {
        for (int i = tid; i < 128 * 16; i += 256) {
            int r = i >> 4, q = (i & 15) * 4;
            int gr = rowBase + r;
            float4 v = make_float4(0.f, 0.f, 0.f, 0.f);
            if (gr < Nn) v = *(const float4*)(x + gr * FIN + h * 64 + q);
            xs[(q + 0) * 132 + r] = v.x;
            xs[(q + 1) * 132 + r] = v.y;
            xs[(q + 2) * 132 + r] = v.z;
            xs[(q + 3) * 132 + r] = v.w;
        }
        __syncthreads();
        #pragma unroll 4
        for (int k = 0; k < 64; k++) {
            float4 a0 = *(const float4*)(xs + k * 132 + r0);
            float4 w0 = *(const float4*)(wk + (h * 64 + k) * 64 + f0);
            float4 w1 = *(const float4*)(wk + (h * 64 + k) * 64 + 32 + f0);
            float av[4] = {a0.x, a0.y, a0.z, a0.w};
            float wv[8] = {w0.x, w0.y, w0.z, w0.w, w1.x, w1.y, w1.z, w1.w};
            #pragma unroll
            for (int i = 0; i < 4; i++)
                #pragma unroll
                for (int j = 0; j < 8; j++)
                    acc[i][j] = fmaf(av[i], wv[j], acc[i][j]);
        }
        __syncthreads();
    }
    {
        float b0[4] = {bs[f0], bs[f0 + 1], bs[f0 + 2], bs[f0 + 3]};
        float b1[4] = {bs[32 + f0], bs[32 + f0 + 1], bs[32 + f0 + 2], bs[32 + f0 + 3]};
        #pragma unroll
        for (int i = 0; i < 4; i++) {
            int gr = rowBase + r0 + i;
            if (gr < Nn) {
                *(float4*)(g_h0 + gr * HID + f0) = make_float4(
                    fmaxf(acc[i][0] + b0[0], 0.f), fmaxf(acc[i][1] + b0[1], 0.f),
                    fmaxf(acc[i][2] + b0[2], 0.f), fmaxf(acc[i][3] + b0[3], 0.f));
                *(float4*)(g_h0 + gr * HID + 32 + f0) = make_float4(
                    fmaxf(acc[i][4] + b1[0], 0.f), fmaxf(acc[i][5] + b1[1], 0.f),
                    fmaxf(acc[i][6] + b1[2], 0.f), fmaxf(acc[i][7] + b1[3], 0.f));
            }
        }
    }
    __syncthreads();

    float* wk1 = wk;
    float* wk2 = wk + 64 * 64;
    for (int i = tid; i < 64 * 16; i += 256) {
        int k = i >> 4, q = (i & 15) * 4;
        float4 w = *(const float4*)(W1 + k * 64 + q);
        float4 v = *(const float4*)(W2 + k * 64 + q);
        int d = k - q;
        if (d >= 0 && d < 4) {
            ((float*)&w)[d] += 1.0f;
            ((float*)&v)[d] += ALPHAc;
        }
        *(float4*)(wk1 + k * 64 + q) = w;
        *(float4*)(wk2 + k * 64 + q) = v;
    }
    for (int i = tid; i < 128 * 16; i += 256) {
        int r = i >> 4, q = (i & 15) * 4;
        int gr = rowBase + r;
        float4 p = make_float4(0.f, 0.f, 0.f, 0.f);
        if (gr < Nn) p = *(const float4*)(g_h0 + gr * HID + q);
        xs[(q + 0) * 132 + r] = p.x;
        xs[(q + 1) * 132 + r] = p.y;
        xs[(q + 2) * 132 + r] = p.z;
        xs[(q + 3) * 132 + r] = p.w;
    }
    __syncthreads();

    #pragma unroll
    for (int i = 0; i < 4; i++)
        #pragma unroll
        for (int j = 0; j < 8; j++) acc[i][j] = 0.0f;
    #pragma unroll 4
    for (int k = 0; k < 64; k++) {
        float4 a0 = *(const float4*)(xs + k * 132 + r0);
        float4 w0 = *(const float4*)(wk1 + k * 64 + f0);
        float4 w1 = *(const float4*)(wk1 + k * 64 + 32 + f0);
        float av[4] = {a0.x, a0.y, a0.z, a0.w};
        float wv[8] = {w0.x, w0.y, w0.z, w0.w, w1.x, w1.y, w1.z, w1.w};
        #pragma unroll
        for (int i = 0; i < 4; i++)
            #pragma unroll
            for (int j = 0; j < 8; j++)
                acc[i][j] = fmaf(av[i], wv[j], acc[i][j]);
    }
    #pragma unroll
    for (int i = 0; i < 4; i++) {
        int gr = rowBase + r0 + i;
        if (gr < Nn) {
            *(float4*)(g_support + gr * HID + f0) =
                make_float4(acc[i][0], acc[i][1], acc[i][2], acc[i][3]);
            *(float4*)(g_support + gr * HID + 32 + f0) =
                make_float4(acc[i][4], acc[i][5], acc[i][6], acc[i][7]);
        }
    }

    #pragma unroll
    for (int i = 0; i < 4; i++)
        #pragma unroll
        for (int j = 0; j < 8; j++) acc[i][j] = 0.0f;
    #pragma unroll 4
    for (int k = 0; k < 64; k++) {
        float4 a0 = *(const float4*)(xs + k * 132 + r0);
        float4 w0 = *(const float4*)(wk2 + k * 64 + f0);
        float4 w1 = *(const float4*)(wk2 + k * 64 + 32 + f0);
        float av[4] = {a0.x, a0.y, a0.z, a0.w};
        float wv[8] = {w0.x, w0.y, w0.z, w0.w, w1.x, w1.y, w1.z, w1.w};
        #pragma unroll
        for (int i = 0; i < 4; i++)
            #pragma unroll
            for (int j = 0; j < 8; j++)
                acc[i][j] = fmaf(av[i], wv[j], acc[i][j]);
    }
    #pragma unroll
    for (int i = 0; i < 4; i++) {
        int gr = rowBase + r0 + i;
        if (gr < Nn) {
            *(float4*)(init0 + gr * HID + f0) =
                make_float4(acc[i][0], acc[i][1], acc[i][2], acc[i][3]);
            *(float4*)(init0 + gr * HID + 32 + f0) =
                make_float4(acc[i][4], acc[i][5], acc[i][6], acc[i][7]);
        }
    }
}

// ------- hp GEMM: support = hp @ (I+W1); hp = BN-applied, to g_hprev -----------
#define GEMM_SMEM (64 * 132 * 4 + 64 * 64 * 4 + 128 * 4)
__global__ __launch_bounds__(256) void k_gemm_hp(const float* __restrict__ W1,
                                                 const float* __restrict__ gamma,
                                                 const float* __restrict__ beta,
                                                 const float* __restrict__ hsrc,
                                                 int apply, int rb, int zb) {
    extern __shared__ float sm[];
    float* xs  = sm;
    float* wk  = sm + 64 * 132;
    float* scs = wk + 64 * 64;
    float* shs = scs + 64;
    int tid = threadIdx.x;
    int rowBase = blockIdx.x * 128;

    if (blockIdx.x == 0 && tid < 2 * HID) g_stats[zb][tid] = 0.0f;

    for (int i = tid; i < 64 * 16; i += 256) {
        int k = i >> 4, q = (i & 15) * 4;
        float4 w = *(const float4*)(W1 + k * 64 + q);
        int d = k - q;
        if (d >= 0 && d < 4) ((float*)&w)[d] += 1.0f;
        *(float4*)(wk + k * 64 + q) = w;
    }
    if (tid < HID) {
        if (apply) {
            float m = g_stats[rb][tid] * (1.0f / Nn);
            float v = g_stats[rb][HID + tid] * (1.0f / Nn) - m * m;
            float inv = rsqrtf(v + EPSBN);
            float scale = gamma[tid] * inv;
            scs[tid] = scale;
            shs[tid] = beta[tid] - m * scale;
        } else {
            scs[tid] = 0.0f;
            shs[tid] = 0.0f;
        }
    }
    __syncthreads();

    if (apply) {
        for (int i = tid; i < 128 * 16; i += 256) {
            int r = i >> 4, q = (i & 15) * 4;
            int gr = rowBase + r;
            float4 p = make_float4(0.f, 0.f, 0.f, 0.f);
            if (gr < Nn) {
                p = *(const float4*)(hsrc + gr * HID + q);
                float4 a = *(const float4*)(g_agg + gr * HID + q);
                p.x += fmaxf(fmaf(a.x, scs[q + 0], shs[q + 0]), 0.f);
                p.y += fmaxf(fmaf(a.y, scs[q + 1], shs[q + 1]), 0.f);
                p.z += fmaxf(fmaf(a.z, scs[q + 2], shs[q + 2]), 0.f);
                p.w += fmaxf(fmaf(a.w, scs[q + 3], shs[q + 3]), 0.f);
                *(float4*)(g_hprev + gr * HID + q) = p;
            }
            xs[(q + 0) * 132 + r] = p.x;
            xs[(q + 1) * 132 + r] = p.y;
            xs[(q + 2) * 132 + r] = p.z;
            xs[(q + 3) * 132 + r] = p.w;
        }
    } else {
        for (int i = tid; i < 128 * 16; i += 256) {
            int r = i >> 4, q = (i & 15) * 4;
            int gr = rowBase + r;
            float4 p = make_float4(0.f, 0.f, 0.f, 0.f);
            if (gr < Nn) p = *(const float4*)(hsrc + gr * HID + q);
            xs[(q + 0) * 132 + r] = p.x;
            xs[(q + 1) * 132 + r] = p.y;
            xs[(q + 2) * 132 + r] = p.z;
            xs[(q + 3) * 132 + r] = p.w;
        }
    }
    __syncthreads();

    int rg = tid >> 3, cg = tid & 7;
    int r0 = rg * 4, f0 = cg * 4;
    float acc[4][8];
    #pragma unroll
    for (int i = 0; i < 4; i++)
        #pragma unroll
        for (int j = 0; j < 8; j++) acc[i][j] = 0.0f;
    #pragma unroll 4
    for (int k = 0; k < 64; k++) {
        float4 a0 = *(const float4*)(xs + k * 132 + r0);
        float4 w0 = *(const float4*)(wk + k * 64 + f0);
        float4 w1 = *(const float4*)(wk + k * 64 + 32 + f0);
        float av[4] = {a0.x, a0.y, a0.z, a0.w};
        float wv[8] = {w0.x, w0.y, w0.z, w0.w, w1.x, w1.y, w1.z, w1.w};
        #pragma unroll
        for (int i = 0; i < 4; i++)
            #pragma unroll
            for (int j = 0; j < 8; j++)
                acc[i][j] = fmaf(av[i], wv[j], acc[i][j]);
    }
    #pragma unroll
    for (int i = 0; i < 4; i++) {
        int gr = rowBase + r0 + i;
        if (gr < Nn) {
            *(float4*)(g_support + gr * HID + f0) =
                make_float4(acc[i][0], acc[i][1], acc[i][2], acc[i][3]);
            *(float4*)(g_support + gr * HID + 32 + f0) =
                make_float4(acc[i][4], acc[i][5], acc[i][6], acc[i][7]);
        }
    }
}

// ------- init GEMMs for layers 1..3, one launch: dst_l = h0 @ (aI + W2_l) ------
__global__ __launch_bounds__(256) void k_gemm_init3(const float* __restrict__ w2base,
                                                    float* __restrict__ initbase) {
    extern __shared__ float sm[];
    float* xs = sm;
    float* wk = sm + 64 * 132;
    int tid = threadIdx.x;
    int layer = blockIdx.x / NTILE + 1;          // 1..3
    int tile = blockIdx.x % NTILE;
    const float* W2 = w2base + layer * HID * HID;
    float* dst = initbase + layer * Nn * HID;
    int rowBase = tile * 128;
    for (int i = tid; i < 64 * 16; i += 256) {
        int k = i >> 4, q = (i & 15) * 4;
        float4 w = *(const float4*)(W2 + k * 64 + q);
        int d = k - q;
        if (d >= 0 && d < 4) ((float*)&w)[d] += ALPHAc;
        *(float4*)(wk + k * 64 + q) = w;
    }
    __syncthreads();
    for (int i = tid; i < 128 * 16; i += 256) {
        int r = i >> 4, q = (i & 15) * 4;
        int gr = rowBase + r;
        float4 p = make_float4(0.f, 0.f, 0.f, 0.f);
        if (gr < Nn) p = *(const float4*)(g_h0 + gr * HID + q);
        xs[(q + 0) * 132 + r] = p.x;
        xs[(q + 1) * 132 + r] = p.y;
        xs[(q + 2) * 132 + r] = p.z;
        xs[(q + 3) * 132 + r] = p.w;
    }
    __syncthreads();
    int rg = tid >> 3, cg = tid & 7;
    int r0 = rg * 4, f0 = cg * 4;
    float acc[4][8];
    #pragma unroll
    for (int i = 0; i < 4; i++)
        #pragma unroll
        for (int j = 0; j < 8; j++) acc[i][j] = 0.0f;
    #pragma unroll 4
    for (int k = 0; k < 64; k++) {
        float4 a0 = *(const float4*)(xs + k * 132 + r0);
        float4 w0 = *(const float4*)(wk + k * 64 + f0);
        float4 w1 = *(const float4*)(wk + k * 64 + 32 + f0);
        float av[4] = {a0.x, a0.y, a0.z, a0.w};
        float wv[8] = {w0.x, w0.y, w0.z, w0.w, w1.x, w1.y, w1.z, w1.w};
        #pragma unroll
        for (int i = 0; i < 4; i++)
            #pragma unroll
            for (int j = 0; j < 8; j++)
                acc[i][j] = fmaf(av[i], wv[j], acc[i][j]);
    }
    #pragma unroll
    for (int i = 0; i < 4; i++) {
        int gr = rowBase + r0 + i;
        if (gr < Nn) {
            *(float4*)(dst + gr * HID + f0) =
                make_float4(acc[i][0], acc[i][1], acc[i][2], acc[i][3]);
            *(float4*)(dst + gr * HID + 32 + f0) =
                make_float4(acc[i][4], acc[i][5], acc[i][6], acc[i][7]);
        }
    }
}

// ---- gather (R12 best): grid-stride warp-per-node, dual-edge prefetch ---------
__device__ __forceinline__ float redgrp(float v) {
    v += __shfl_xor_sync(0xffffffffu, v, 8);
    v += __shfl_xor_sync(0xffffffffu, v, 16);
    return v;
}

__global__ __launch_bounds__(256) void k_gather(int wb, const float* __restrict__ initp) {
    __shared__ float4 s_sA[8][8], s_sB[8][8], s_qA[8][8], s_qB[8][8];
    int tid = threadIdx.x;
    int wid = tid >> 5, lane = tid & 31;
    int grp = lane >> 3;
    int sub = lane & 7;
    int q = sub * 8;
    float4 lsA = make_float4(0.f, 0.f, 0.f, 0.f), lsB = lsA, lqA = lsA, lqB = lsA;
    const int nwarps = gridDim.x * 8;
    for (int n = blockIdx.x * 8 + wid; n < Nn; n += nwarps) {
        float4 aA, aB;
        if (grp == 0) {
            float d = g_dinv[n];
            float swt = d * d;
            aA = *(const float4*)(initp + n * HID + q);
            aB = *(const float4*)(initp + n * HID + q + 4);
            float4 sA = *(const float4*)(g_support + n * HID + q);
            float4 sB = *(const float4*)(g_support + n * HID + q + 4);
            aA.x = fmaf(swt, sA.x, aA.x); aA.y = fmaf(swt, sA.y, aA.y);
            aA.z = fmaf(swt, sA.z, aA.z); aA.w = fmaf(swt, sA.w, aA.w);
            aB.x = fmaf(swt, sB.x, aB.x); aB.y = fmaf(swt, sB.y, aB.y);
            aB.z = fmaf(swt, sB.z, aB.z); aB.w = fmaf(swt, sB.w, aB.w);
        } else {
            aA = make_float4(0.f, 0.f, 0.f, 0.f);
            aB = aA;
        }
        int p0 = g_rowptr[n], p1 = g_rowptr[n + 1];
        int p = p0 + grp;
        int2 e0 = make_int2(0, 0), e1 = make_int2(0, 0);
        if (p < p1) {
            e0 = __ldg(&g_eidx[p]);
            if (p + 4 < p1) e1 = __ldg(&g_eidx[p + 4]);
        }
        while (p < p1) {
            int pn = p + 8;
            int2 n0 = make_int2(0, 0), n1 = make_int2(0, 0);
            if (pn < p1) {
                n0 = __ldg(&g_eidx[pn]);
                if (pn + 4 < p1) n1 = __ldg(&g_eidx[pn + 4]);
            }
            float w0 = __int_as_float(e0.y);
            float w1 = __int_as_float(e1.y);
            float4 sA0 = __ldg((const float4*)(g_support + e0.x + q));
            float4 sB0 = __ldg((const float4*)(g_support + e0.x + q + 4));
            float4 sA1 = __ldg((const float4*)(g_support + e1.x + q));
            float4 sB1 = __ldg((const float4*)(g_support + e1.x + q + 4));
            aA.x = fmaf(w0, sA0.x, aA.x); aA.y = fmaf(w0, sA0.y, aA.y);
            aA.z = fmaf(w0, sA0.z, aA.z); aA.w = fmaf(w0, sA0.w, aA.w);
            aB.x = fmaf(w0, sB0.x, aB.x); aB.y = fmaf(w0, sB0.y, aB.y);
            aB.z = fmaf(w0, sB0.z, aB.z); aB.w = fmaf(w0, sB0.w, aB.w);
            aA.x = fmaf(w1, sA1.x, aA.x); aA.y = fmaf(w1, sA1.y, aA.y);
            aA.z = fmaf(w1, sA1.z, aA.z); aA.w = fmaf(w1, sA1.w, aA.w);
            aB.x = fmaf(w1, sB1.x, aB.x); aB.y = fmaf(w1, sB1.y, aB.y);
            aB.z = fmaf(w1, sB1.z, aB.z); aB.w = fmaf(w1, sB1.w, aB.w);
            e0 = n0; e1 = n1; p = pn;
        }
        aA.x = redgrp(aA.x); aA.y = redgrp(aA.y); aA.z = redgrp(aA.z); aA.w = redgrp(aA.w);
        aB.x = redgrp(aB.x); aB.y = redgrp(aB.y); aB.z = redgrp(aB.z); aB.w = redgrp(aB.w);
        if (grp == 0) {
            *(float4*)(g_agg + n * HID + q)     = aA;
            *(float4*)(g_agg + n * HID + q + 4) = aB;
            lsA.x += aA.x; lsA.y += aA.y; lsA.z += aA.z; lsA.w += aA.w;
            lsB.x += aB.x; lsB.y += aB.y; lsB.z += aB.z; lsB.w += aB.w;
            lqA.x += aA.x * aA.x; lqA.y += aA.y * aA.y;
            lqA.z += aA.z * aA.z; lqA.w += aA.w * aA.w;
            lqB.x += aB.x * aB.x; lqB.y += aB.y * aB.y;
            lqB.z += aB.z * aB.z; lqB.w += aB.w * aB.w;
        }
    }
    if (grp == 0) {
        s_sA[wid][sub] = lsA; s_sB[wid][sub] = lsB;
        s_qA[wid][sub] = lqA; s_qB[wid][sub] = lqB;
    }
    __syncthreads();
    if (tid < 8) {
        float4 a = s_sA[0][tid], b = s_sB[0][tid];
        float4 c = s_qA[0][tid], d = s_qB[0][tid];
        #pragma unroll
        for (int wv = 1; wv < 8; wv++) {
            float4 t;
            t = s_sA[wv][tid]; a.x += t.x; a.y += t.y; a.z += t.z; a.w += t.w;
            t = s_sB[wv][tid]; b.x += t.x; b.y += t.y; b.z += t.z; b.w += t.w;
            t = s_qA[wv][tid]; c.x += t.x; c.y += t.y; c.z += t.z; c.w += t.w;
            t = s_qB[wv][tid]; d.x += t.x; d.y += t.y; d.z += t.z; d.w += t.w;
        }
        float* st = g_stats[wb];
        int base = tid * 8;
        atomicAdd(&st[base + 0], a.x); atomicAdd(&st[base + 1], a.y);
        atomicAdd(&st[base + 2], a.z); atomicAdd(&st[base + 3], a.w);
        atomicAdd(&st[base + 4], b.x); atomicAdd(&st[base + 5], b.y);
        atomicAdd(&st[base + 6], b.z); atomicAdd(&st[base + 7], b.w);
        atomicAdd(&st[HID + base + 0], c.x); atomicAdd(&st[HID + base + 1], c.y);
        atomicAdd(&st[HID + base + 2], c.z); atomicAdd(&st[HID + base + 3], c.w);
        atomicAdd(&st[HID + base + 4], d.x); atomicAdd(&st[HID + base + 5], d.y);
        atomicAdd(&st[HID + base + 6], d.z); atomicAdd(&st[HID + base + 7], d.w);
    }
}

// ---------------- output GEMM with fused final BN ------------------------------
__global__ __launch_bounds__(256) void k_outgemm(const float* __restrict__ Wo,
                                                 const float* __restrict__ bo,
                                                 const float* __restrict__ gamma,
                                                 const float* __restrict__ beta,
                                                 int rb,
                                                 float* __restrict__ out) {
    __shared__ float Ws[HID * OUTF];
    __shared__ float bs[OUTF];
    __shared__ float hp[32][HID];
    __shared__ float scs[HID];
    __shared__ float shs[HID];
    int tid = threadIdx.x;
    for (int i = tid; i < HID * OUTF; i += 256) Ws[i] = Wo[i];
    if (tid < OUTF) bs[tid] = bo[tid];
    if (tid < HID) {
        float m = g_stats[rb][tid] * (1.0f / Nn);
        float v = g_stats[rb][HID + tid] * (1.0f / Nn) - m * m;
        float inv = rsqrtf(v + EPSBN);
        float scale = gamma[tid] * inv;
        scs[tid] = scale;
        shs[tid] = beta[tid] - m * scale;
    }
    __syncthreads();
    int rowBase = blockIdx.x * 32;
    for (int i = tid; i < 32 * HID; i += 256) {
        int rr = i >> 6, f = i & 63;
        int gr = rowBase + rr;
        float hv = g_hprev[gr * HID + f]
                 + fmaxf(fmaf(g_agg[gr * HID + f], scs[f], shs[f]), 0.0f);
        hp[rr][f] = hv;
    }
    __syncthreads();
    for (int idx = tid; idx < 32 * OUTF; idx += 256) {
        int rr = idx / OUTF, f = idx % OUTF;
        int gr = rowBase + rr;
        float acc = bs[f];
        #pragma unroll
        for (int k = 0; k < HID; k++) acc += hp[rr][k] * Ws[k * OUTF + f];
        out[gr * OUTF + f] = acc;
    }
}

// ---------------- launch --------------------------------------------------------
extern "C" void kernel_launch(void* const* d_in, const int* in_sizes, int n_in,
                              void* d_out, int out_size) {
    const float* x     = (const float*)d_in[0];
    const void*  ei    = d_in[1];
    const float* Wi    = (const float*)d_in[2];
    const float* bi    = (const float*)d_in[3];
    const float* w1    = (const float*)d_in[4];
    const float* w2    = (const float*)d_in[5];
    const float* gamma = (const float*)d_in[6];
    const float* beta  = (const float*)d_in[7];
    const float* Wo    = (const float*)d_in[8];
    const float* bo    = (const float*)d_in[9];
    float* out = (float*)d_out;

    static cudaStream_t s1 = nullptr, s2 = nullptr;
    static cudaEvent_t ev0, evF, evCsr, evI, evDone;
    if (!s1) {
        cudaStreamCreateWithFlags(&s1, cudaStreamNonBlocking);
        cudaStreamCreateWithFlags(&s2, cudaStreamNonBlocking);
        cudaEventCreateWithFlags(&ev0,    cudaEventDisableTiming);
        cudaEventCreateWithFlags(&evF,    cudaEventDisableTiming);
        cudaEventCreateWithFlags(&evCsr,  cudaEventDisableTiming);
        cudaEventCreateWithFlags(&evI,    cudaEventDisableTiming);
        cudaEventCreateWithFlags(&evDone, cudaEventDisableTiming);
        cudaFuncSetAttribute(k_fused0, cudaFuncAttributeMaxDynamicSharedMemorySize,
                             FUSED_SMEM);
        cudaFuncSetAttribute(k_gemm_hp, cudaFuncAttributeMaxDynamicSharedMemorySize,
                             GEMM_SMEM);
        cudaFuncSetAttribute(k_gemm_init3, cudaFuncAttributeMaxDynamicSharedMemorySize,
                             GEMM_SMEM);
    }

    void* cnt_ptr = nullptr;
    void* stats_ptr = nullptr;
    cudaGetSymbolAddress(&cnt_ptr, g_cnt);
    cudaGetSymbolAddress(&stats_ptr, g_stats);
    float* initp = nullptr;
    cudaGetSymbolAddress((void**)&initp, g_init);
    const float* h0p = nullptr;
    cudaGetSymbolAddress((void**)&h0p, g_h0);
    const float* hpp = nullptr;
    cudaGetSymbolAddress((void**)&hpp, g_hprev);

    // fork both worker streams from the origin stream
    cudaMemsetAsync(cnt_ptr, 0, Nn * sizeof(int));
    cudaMemsetAsync(stats_ptr, 0, 4 * HID * sizeof(float));
    cudaEventRecord(ev0, 0);
    cudaStreamWaitEvent(s1, ev0, 0);
    cudaStreamWaitEvent(s2, ev0, 0);

    // s1: fused prologue (h0, support0, init0)
    k_fused0<<<NTILE, 256, FUSED_SMEM, s1>>>(x, Wi, bi, w1, w2, initp);
    cudaEventRecord(evF, s1);

    // s2: CSR build, then all init GEMMs for layers 1-3
    k_deg<<<(Ee + 255) / 256, 256, 0, s2>>>(ei);
    k_bsum<<<NB_SCAN, 256, 0, s2>>>();
    k_bscan<<<1, 512, 0, s2>>>();
    k_rowptr<<<NB_SCAN, 256, 0, s2>>>();
    k_fill<<<(Ee + 255) / 256, 256, 0, s2>>>(ei);
    cudaEventRecord(evCsr, s2);
    cudaStreamWaitEvent(s2, evF, 0);
    k_gemm_init3<<<3 * NTILE, 256, GEMM_SMEM, s2>>>(w2, initp);
    cudaEventRecord(evI, s2);

    // s1: layer chain
    cudaStreamWaitEvent(s1, evCsr, 0);
    k_gather<<<592, 256, 0, s1>>>(0, initp);
    for (int l = 1; l < NL; l++) {
        int wb = l & 1;
        int rb = (l - 1) & 1;
        const float* hs = (l == 1) ? h0p : hpp;
        k_gemm_hp<<<NTILE, 256, GEMM_SMEM, s1>>>(w1 + l * HID * HID,
                                                 gamma + (l - 1) * HID,
                                                 beta + (l - 1) * HID, hs, 1, rb, wb);
        if (l == 1) cudaStreamWaitEvent(s1, evI, 0);
        k_gather<<<592, 256, 0, s1>>>(wb, initp + l * Nn * HID);
    }
    k_outgemm<<<Nn / 32, 256, 0, s1>>>(Wo, bo, gamma + (NL - 1) * HID,
                                       beta + (NL - 1) * HID, (NL - 1) & 1, out);

    // join back to origin stream
    cudaEventRecord(evDone, s1);
    cudaStreamWaitEvent(0, evDone, 0);
}

// round 17
// speedup vs baseline: 1.0164x; 1.0164x over previous
#include <cuda_runtime.h>
#include <cuda_fp16.h>
#include <cstdint>

#define Nn   100000
#define Ee   1000000
#define FIN  128
#define HID  64
#define OUTF 40
#define NL   4
#define ALPHAc 0.5f
#define EPSBN  1e-5f

#define NB_SCAN ((Nn + 255) / 256)   // 391
#define NTILE   ((Nn + 127) / 128)   // 782

// ---------------- scratch ----------------------------------------------------
__device__ __align__(16) float g_h0[Nn * HID];
__device__ __align__(16) float g_hprev[Nn * HID];
__device__ __align__(16) __half g_supph[Nn * HID];   // fp16 support (gather input)
__device__ __align__(16) float g_agg[Nn * HID];
__device__ __align__(16) float g_init[NL][Nn * HID];
__device__ float g_dinv[Nn];
__device__ float g_stats[2][2 * HID];
__device__ int   g_cnt[Nn];
__device__ int   g_bsum[NB_SCAN];
__device__ int   g_boff[NB_SCAN];
__device__ int   g_rowptr[Nn + 1];
__device__ int   g_cur[Nn];
__device__ __align__(8) int2 g_eidx[Ee];

// ---------------- edge index dtype handling -----------------------------------
__device__ __forceinline__ int detect64(const void* ei) {
    const long long* p = (const long long*)ei;
    int ok = 1;
    #pragma unroll
    for (int j = 0; j < 8; j++) {
        long long v = p[j];
        if (v < 0 || v >= Nn) ok = 0;
    }
    return ok;
}
__device__ __forceinline__ int edge_at(const void* ei, int is64, int idx) {
    if (is64) return (int)((const long long*)ei)[idx];
    return ((const int*)ei)[idx];
}

// ---------------- CSR build ----------------------------------------------------
__global__ void k_deg(const void* ei) {
    __shared__ int s64;
    if (threadIdx.x == 0) s64 = detect64(ei);
    __syncthreads();
    int e = blockIdx.x * blockDim.x + threadIdx.x;
    if (e < Ee) {
        int c = edge_at(ei, s64, Ee + e);
        atomicAdd(&g_cnt[c], 1);
    }
}

__global__ void k_bsum() {
    __shared__ int s[256];
    int t = threadIdx.x;
    int i = blockIdx.x * 256 + t;
    s[t] = (i < Nn) ? g_cnt[i] : 0;
    __syncthreads();
    for (int st = 128; st > 0; st >>= 1) {
        if (t < st) s[t] += s[t + st];
        __syncthreads();
    }
    if (t == 0) g_bsum[blockIdx.x] = s[0];
}

__global__ void k_bscan() {
    __shared__ int s[512];
    int t = threadIdx.x;
    int orig = (t < NB_SCAN) ? g_bsum[t] : 0;
    s[t] = orig;
    __syncthreads();
    for (int off = 1; off < 512; off <<= 1) {
        int v = (t >= off) ? s[t - off] : 0;
        __syncthreads();
        s[t] += v;
        __syncthreads();
    }
    if (t < NB_SCAN) g_boff[t] = s[t] - orig;
}

__global__ void k_rowptr() {
    __shared__ int s[256];
    int t = threadIdx.x;
    int i = blockIdx.x * 256 + t;
    int orig = (i < Nn) ? g_cnt[i] : 0;
    s[t] = orig;
    __syncthreads();
    for (int off = 1; off < 256; off <<= 1) {
        int v = (t >= off) ? s[t - off] : 0;
        __syncthreads();
        s[t] += v;
        __syncthreads();
    }
    if (i < Nn) {
        int rp = g_boff[blockIdx.x] + s[t] - orig;
        g_rowptr[i] = rp;
        g_cur[i] = rp;
        g_dinv[i] = rsqrtf((float)orig + 1.0f);
    }
    if (i == 0) g_rowptr[Nn] = Ee;
}

__global__ void k_fill(const void* __restrict__ ei) {
    __shared__ int s64;
    if (threadIdx.x == 0) s64 = detect64(ei);
    __syncthreads();
    int e = blockIdx.x * blockDim.x + threadIdx.x;
    if (e < Ee) {
        int r = edge_at(ei, s64, e);
        int c = edge_at(ei, s64, Ee + e);
        float w = g_dinv[r] * g_dinv[c];
        int pos = atomicAdd(&g_cur[c], 1);
        g_eidx[pos] = make_int2(r * HID, __float_as_int(w));
    }
}

// ---- half store helper: 4 floats -> 8 bytes ----
__device__ __forceinline__ void store_h4(__half* dst, float a, float b, float c, float d) {
    __half2 p01 = __floats2half2_rn(a, b);
    __half2 p23 = __floats2half2_rn(c, d);
    uint2 st;
    st.x = *(unsigned*)&p01;
    st.y = *(unsigned*)&p23;
    *(uint2*)dst = st;
}

// ---- fused prologue: h0 = relu(x@Wi+bi); supph0 = h0@(I+W1); init0 = h0@(aI+W2)
#define FUSED_SMEM (64 * 132 * 4 + 128 * 64 * 4 + 64 * 4)
__global__ __launch_bounds__(256) void k_fused0(const float* __restrict__ x,
                                                const float* __restrict__ Wi,
                                                const float* __restrict__ bi,
                                                const float* __restrict__ W1,
                                                const float* __restrict__ W2,
                                                float* __restrict__ init0) {
    extern __shared__ float sm[];
    float* xs = sm;              // [64][132]
    float* wk = sm + 64 * 132;   // phase A: Wi; phase B: W1 | W2
    float* bs = wk + 128 * 64;
    int tid = threadIdx.x;
    int rowBase = blockIdx.x * 128;
    for (int i = tid; i < 128 * 16; i += 256)
        *(float4*)(wk + i * 4) = *(const float4*)(Wi + i * 4);
    if (tid < HID) bs[tid] = bi[tid];
    __syncthreads();

    int rg = tid >> 3, cg = tid & 7;
    int r0 = rg * 4, f0 = cg * 4;
    float acc[4][8];
    #pragma unroll
    for (int i = 0; i < 4; i++)
        #pragma unroll
        for (int j = 0; j < 8; j++) acc[i][j] = 0.0f;

    for (int h = 0; h < 2; h++) {
        for (int i = tid; i < 128 * 16; i += 256) {
            int r = i >> 4, q = (i & 15) * 4;
            int gr = rowBase + r;
            float4 v = make_float4(0.f, 0.f, 0.f, 0.f);
            if (gr < Nn) v = *(const float4*)(x + gr * FIN + h * 64 + q);
            xs[(q + 0) * 132 + r] = v.x;
            xs[(q + 1) * 132 + r] = v.y;
            xs[(q + 2) * 132 + r] = v.z;
            xs[(q + 3) * 132 + r] = v.w;
        }
        __syncthreads();
        #pragma unroll 4
        for (int k = 0; k < 64; k++) {
            float4 a0 = *(const float4*)(xs + k * 132 + r0);
            float4 w0 = *(const float4*)(wk + (h * 64 + k) * 64 + f0);
            float4 w1 = *(const float4*)(wk + (h * 64 + k) * 64 + 32 + f0);
            float av[4] = {a0.x, a0.y, a0.z, a0.w};
            float wv[8] = {w0.x, w0.y, w0.z, w0.w, w1.x, w1.y, w1.z, w1.w};
            #pragma unroll
            for (int i = 0; i < 4; i++)
                #pragma unroll
                for (int j = 0; j < 8; j++)
                    acc[i][j] = fmaf(av[i], wv[j], acc[i][j]);
        }
        __syncthreads();
    }
    {
        float b0[4] = {bs[f0], bs[f0 + 1], bs[f0 + 2], bs[f0 + 3]};
        float b1[4] = {bs[32 + f0], bs[32 + f0 + 1], bs[32 + f0 + 2], bs[32 + f0 + 3]};
        #pragma unroll
        for (int i = 0; i < 4; i++) {
            int gr = rowBase + r0 + i;
            if (gr < Nn) {
                *(float4*)(g_h0 + gr * HID + f0) = make_float4(
                    fmaxf(acc[i][0] + b0[0], 0.f), fmaxf(acc[i][1] + b0[1], 0.f),
                    fmaxf(acc[i][2] + b0[2], 0.f), fmaxf(acc[i][3] + b0[3], 0.f));
                *(float4*)(g_h0 + gr * HID + 32 + f0) = make_float4(
                    fmaxf(acc[i][4] + b1[0], 0.f), fmaxf(acc[i][5] + b1[1], 0.f),
                    fmaxf(acc[i][6] + b1[2], 0.f), fmaxf(acc[i][7] + b1[3], 0.f));
            }
        }
    }
    __syncthreads();

    float* wk1 = wk;
    float* wk2 = wk + 64 * 64;
    for (int i = tid; i < 64 * 16; i += 256) {
        int k = i >> 4, q = (i & 15) * 4;
        float4 w = *(const float4*)(W1 + k * 64 + q);
        float4 v = *(const float4*)(W2 + k * 64 + q);
        int d = k - q;
        if (d >= 0 && d < 4) {
            ((float*)&w)[d] += 1.0f;
            ((float*)&v)[d] += ALPHAc;
        }
        *(float4*)(wk1 + k * 64 + q) = w;
        *(float4*)(wk2 + k * 64 + q) = v;
    }
    for (int i = tid; i < 128 * 16; i += 256) {
        int r = i >> 4, q = (i & 15) * 4;
        int gr = rowBase + r;
        float4 p = make_float4(0.f, 0.f, 0.f, 0.f);
        if (gr < Nn) p = *(const float4*)(g_h0 + gr * HID + q);
        xs[(q + 0) * 132 + r] = p.x;
        xs[(q + 1) * 132 + r] = p.y;
        xs[(q + 2) * 132 + r] = p.z;
        xs[(q + 3) * 132 + r] = p.w;
    }
    __syncthreads();

    #pragma unroll
    for (int i = 0; i < 4; i++)
        #pragma unroll
        for (int j = 0; j < 8; j++) acc[i][j] = 0.0f;
    #pragma unroll 4
    for (int k = 0; k < 64; k++) {
        float4 a0 = *(const float4*)(xs + k * 132 + r0);
        float4 w0 = *(const float4*)(wk1 + k * 64 + f0);
        float4 w1 = *(const float4*)(wk1 + k * 64 + 32 + f0);
        float av[4] = {a0.x, a0.y, a0.z, a0.w};
        float wv[8] = {w0.x, w0.y, w0.z, w0.w, w1.x, w1.y, w1.z, w1.w};
        #pragma unroll
        for (int i = 0; i < 4; i++)
            #pragma unroll
            for (int j = 0; j < 8; j++)
                acc[i][j] = fmaf(av[i], wv[j], acc[i][j]);
    }
    #pragma unroll
    for (int i = 0; i < 4; i++) {
        int gr = rowBase + r0 + i;
        if (gr < Nn) {
            store_h4(g_supph + gr * HID + f0, acc[i][0], acc[i][1], acc[i][2], acc[i][3]);
            store_h4(g_supph + gr * HID + 32 + f0, acc[i][4], acc[i][5], acc[i][6], acc[i][7]);
        }
    }

    #pragma unroll
    for (int i = 0; i < 4; i++)
        #pragma unroll
        for (int j = 0; j < 8; j++) acc[i][j] = 0.0f;
    #pragma unroll 4
    for (int k = 0; k < 64; k++) {
        float4 a0 = *(const float4*)(xs + k * 132 + r0);
        float4 w0 = *(const float4*)(wk2 + k * 64 + f0);
        float4 w1 = *(const float4*)(wk2 + k * 64 + 32 + f0);
        float av[4] = {a0.x, a0.y, a0.z, a0.w};
        float wv[8] = {w0.x, w0.y, w0.z, w0.w, w1.x, w1.y, w1.z, w1.w};
        #pragma unroll
        for (int i = 0; i < 4; i++)
            #pragma unroll
            for (int j = 0; j < 8; j++)
                acc[i][j] = fmaf(av[i], wv[j], acc[i][j]);
    }
    #pragma unroll
    for (int i = 0; i < 4; i++) {
        int gr = rowBase + r0 + i;
        if (gr < Nn) {
            *(float4*)(init0 + gr * HID + f0) =
                make_float4(acc[i][0], acc[i][1], acc[i][2], acc[i][3]);
            *(float4*)(init0 + gr * HID + 32 + f0) =
                make_float4(acc[i][4], acc[i][5], acc[i][6], acc[i][7]);
        }
    }
}

// ------- hp GEMM: supph = hp @ (I+W1) in fp16; hp = BN-applied, to g_hprev -----
#define GEMM_SMEM (64 * 132 * 4 + 64 * 64 * 4 + 128 * 4)
__global__ __launch_bounds__(256) void k_gemm_hp(const float* __restrict__ W1,
                                                 const float* __restrict__ gamma,
                                                 const float* __restrict__ beta,
                                                 const float* __restrict__ hsrc,
                                                 int rb, int zb) {
    extern __shared__ float sm[];
    float* xs  = sm;
    float* wk  = sm + 64 * 132;
    float* scs = wk + 64 * 64;
    float* shs = scs + 64;
    int tid = threadIdx.x;
    int rowBase = blockIdx.x * 128;

    if (blockIdx.x == 0 && tid < 2 * HID) g_stats[zb][tid] = 0.0f;

    for (int i = tid; i < 64 * 16; i += 256) {
        int k = i >> 4, q = (i & 15) * 4;
        float4 w = *(const float4*)(W1 + k * 64 + q);
        int d = k - q;
        if (d >= 0 && d < 4) ((float*)&w)[d] += 1.0f;
        *(float4*)(wk + k * 64 + q) = w;
    }
    if (tid < HID) {
        float m = g_stats[rb][tid] * (1.0f / Nn);
        float v = g_stats[rb][HID + tid] * (1.0f / Nn) - m * m;
        float inv = rsqrtf(v + EPSBN);
        float scale = gamma[tid] * inv;
        scs[tid] = scale;
        shs[tid] = beta[tid] - m * scale;
    }
    __syncthreads();

    for (int i = tid; i < 128 * 16; i += 256) {
        int r = i >> 4, q = (i & 15) * 4;
        int gr = rowBase + r;
        float4 p = make_float4(0.f, 0.f, 0.f, 0.f);
        if (gr < Nn) {
            p = *(const float4*)(hsrc + gr * HID + q);
            float4 a = *(const float4*)(g_agg + gr * HID + q);
            p.x += fmaxf(fmaf(a.x, scs[q + 0], shs[q + 0]), 0.f);
            p.y += fmaxf(fmaf(a.y, scs[q + 1], shs[q + 1]), 0.f);
            p.z += fmaxf(fmaf(a.z, scs[q + 2], shs[q + 2]), 0.f);
            p.w += fmaxf(fmaf(a.w, scs[q + 3], shs[q + 3]), 0.f);
            *(float4*)(g_hprev + gr * HID + q) = p;
        }
        xs[(q + 0) * 132 + r] = p.x;
        xs[(q + 1) * 132 + r] = p.y;
        xs[(q + 2) * 132 + r] = p.z;
        xs[(q + 3) * 132 + r] = p.w;
    }
    __syncthreads();

    int rg = tid >> 3, cg = tid & 7;
    int r0 = rg * 4, f0 = cg * 4;
    float acc[4][8];
    #pragma unroll
    for (int i = 0; i < 4; i++)
        #pragma unroll
        for (int j = 0; j < 8; j++) acc[i][j] = 0.0f;
    #pragma unroll 4
    for (int k = 0; k < 64; k++) {
        float4 a0 = *(const float4*)(xs + k * 132 + r0);
        float4 w0 = *(const float4*)(wk + k * 64 + f0);
        float4 w1 = *(const float4*)(wk + k * 64 + 32 + f0);
        float av[4] = {a0.x, a0.y, a0.z, a0.w};
        float wv[8] = {w0.x, w0.y, w0.z, w0.w, w1.x, w1.y, w1.z, w1.w};
        #pragma unroll
        for (int i = 0; i < 4; i++)
            #pragma unroll
            for (int j = 0; j < 8; j++)
                acc[i][j] = fmaf(av[i], wv[j], acc[i][j]);
    }
    #pragma unroll
    for (int i = 0; i < 4; i++) {
        int gr = rowBase + r0 + i;
        if (gr < Nn) {
            store_h4(g_supph + gr * HID + f0, acc[i][0], acc[i][1], acc[i][2], acc[i][3]);
            store_h4(g_supph + gr * HID + 32 + f0, acc[i][4], acc[i][5], acc[i][6], acc[i][7]);
        }
    }
}

// ------- init GEMMs for layers 1..3, one launch: dst_l = h0 @ (aI + W2_l) ------
__global__ __launch_bounds__(256) void k_gemm_init3(const float* __restrict__ w2base,
                                                    float* __restrict__ initbase) {
    extern __shared__ float sm[];
    float* xs = sm;
    float* wk = sm + 64 * 132;
    int tid = threadIdx.x;
    int layer = blockIdx.x / NTILE + 1;
    int tile = blockIdx.x % NTILE;
    const float* W2 = w2base + layer * HID * HID;
    float* dst = initbase + layer * Nn * HID;
    int rowBase = tile * 128;
    for (int i = tid; i < 64 * 16; i += 256) {
        int k = i >> 4, q = (i & 15) * 4;
        float4 w = *(const float4*)(W2 + k * 64 + q);
        int d = k - q;
        if (d >= 0 && d < 4) ((float*)&w)[d] += ALPHAc;
        *(float4*)(wk + k * 64 + q) = w;
    }
    __syncthreads();
    for (int i = tid; i < 128 * 16; i += 256) {
        int r = i >> 4, q = (i & 15) * 4;
        int gr = rowBase + r;
        float4 p = make_float4(0.f, 0.f, 0.f, 0.f);
        if (gr < Nn) p = *(const float4*)(g_h0 + gr * HID + q);
        xs[(q + 0) * 132 + r] = p.x;
        xs[(q + 1) * 132 + r] = p.y;
        xs[(q + 2) * 132 + r] = p.z;
        xs[(q + 3) * 132 + r] = p.w;
    }
    __syncthreads();
    int rg = tid >> 3, cg = tid & 7;
    int r0 = rg * 4, f0 = cg * 4;
    float acc[4][8];
    #pragma unroll
    for (int i = 0; i < 4; i++)
        #pragma unroll
        for (int j = 0; j < 8; j++) acc[i][j] = 0.0f;
    #pragma unroll 4
    for (int k = 0; k < 64; k++) {
        float4 a0 = *(const float4*)(xs + k * 132 + r0);
        float4 w0 = *(const float4*)(wk + k * 64 + f0);
        float4 w1 = *(const float4*)(wk + k * 64 + 32 + f0);
        float av[4] = {a0.x, a0.y, a0.z, a0.w};
        float wv[8] = {w0.x, w0.y, w0.z, w0.w, w1.x, w1.y, w1.z, w1.w};
        #pragma unroll
        for (int i = 0; i < 4; i++)
            #pragma unroll
            for (int j = 0; j < 8; j++)
                acc[i][j] = fmaf(av[i], wv[j], acc[i][j]);
    }
    #pragma unroll
    for (int i = 0; i < 4; i++) {
        int gr = rowBase + r0 + i;
        if (gr < Nn) {
            *(float4*)(dst + gr * HID + f0) =
                make_float4(acc[i][0], acc[i][1], acc[i][2], acc[i][3]);
            *(float4*)(dst + gr * HID + 32 + f0) =
                make_float4(acc[i][4], acc[i][5], acc[i][6], acc[i][7]);
        }
    }
}

// ---- gather: warp-per-node over fp16 support rows (128B = one cache line) -----
__device__ __forceinline__ float redgrp(float v) {
    v += __shfl_xor_sync(0xffffffffu, v, 8);
    v += __shfl_xor_sync(0xffffffffu, v, 16);
    return v;
}
__device__ __forceinline__ void cvt8(const uint4& h, float* f) {
    __half2 a = *(const __half2*)&h.x;
    __half2 b = *(const __half2*)&h.y;
    __half2 c = *(const __half2*)&h.z;
    __half2 d = *(const __half2*)&h.w;
    float2 fa = __half22float2(a), fb = __half22float2(b);
    float2 fc = __half22float2(c), fd = __half22float2(d);
    f[0] = fa.x; f[1] = fa.y; f[2] = fb.x; f[3] = fb.y;
    f[4] = fc.x; f[5] = fc.y; f[6] = fd.x; f[7] = fd.y;
}

__global__ __launch_bounds__(256) void k_gather(int wb, const float* __restrict__ initp) {
    __shared__ float4 s_sA[8][8], s_sB[8][8], s_qA[8][8], s_qB[8][8];
    int tid = threadIdx.x;
    int wid = tid >> 5, lane = tid & 31;
    int grp = lane >> 3;
    int sub = lane & 7;
    int q = sub * 8;                 // 8 features per lane
    float4 lsA = make_float4(0.f, 0.f, 0.f, 0.f), lsB = lsA, lqA = lsA, lqB = lsA;
    const int nwarps = gridDim.x * 8;
    for (int n = blockIdx.x * 8 + wid; n < Nn; n += nwarps) {
        float aA[4] = {0.f, 0.f, 0.f, 0.f};
        float aB[4] = {0.f, 0.f, 0.f, 0.f};
        if (grp == 0) {
            float d = g_dinv[n];
            float swt = d * d;
            float4 i0 = *(const float4*)(initp + n * HID + q);
            float4 i1 = *(const float4*)(initp + n * HID + q + 4);
            uint4 hv = *(const uint4*)(g_supph + n * HID + q);
            float sf[8];
            cvt8(hv, sf);
            aA[0] = fmaf(swt, sf[0], i0.x); aA[1] = fmaf(swt, sf[1], i0.y);
            aA[2] = fmaf(swt, sf[2], i0.z); aA[3] = fmaf(swt, sf[3], i0.w);
            aB[0] = fmaf(swt, sf[4], i1.x); aB[1] = fmaf(swt, sf[5], i1.y);
            aB[2] = fmaf(swt, sf[6], i1.z); aB[3] = fmaf(swt, sf[7], i1.w);
        }
        int p0 = g_rowptr[n], p1 = g_rowptr[n + 1];
        int p = p0 + grp;
        int2 e0 = make_int2(0, 0), e1 = make_int2(0, 0);
        if (p < p1) {
            e0 = __ldg(&g_eidx[p]);
            if (p + 4 < p1) e1 = __ldg(&g_eidx[p + 4]);
        }
        while (p < p1) {
            int pn = p + 8;
            int2 n0 = make_int2(0, 0), n1 = make_int2(0, 0);
            if (pn < p1) {
                n0 = __ldg(&g_eidx[pn]);
                if (pn + 4 < p1) n1 = __ldg(&g_eidx[pn + 4]);
            }
            float w0 = __int_as_float(e0.y);
            float w1 = __int_as_float(e1.y);
            uint4 h0 = __ldg((const uint4*)(g_supph + e0.x + q));
            uint4 h1 = __ldg((const uint4*)(g_supph + e1.x + q));
            float s0[8], s1[8];
            cvt8(h0, s0);
            cvt8(h1, s1);
            aA[0] = fmaf(w0, s0[0], aA[0]); aA[1] = fmaf(w0, s0[1], aA[1]);
            aA[2] = fmaf(w0, s0[2], aA[2]); aA[3] = fmaf(w0, s0[3], aA[3]);
            aB[0] = fmaf(w0, s0[4], aB[0]); aB[1] = fmaf(w0, s0[5], aB[1]);
            aB[2] = fmaf(w0, s0[6], aB[2]); aB[3] = fmaf(w0, s0[7], aB[3]);
            aA[0] = fmaf(w1, s1[0], aA[0]); aA[1] = fmaf(w1, s1[1], aA[1]);
            aA[2] = fmaf(w1, s1[2], aA[2]); aA[3] = fmaf(w1, s1[3], aA[3]);
            aB[0] = fmaf(w1, s1[4], aB[0]); aB[1] = fmaf(w1, s1[5], aB[1]);
            aB[2] = fmaf(w1, s1[6], aB[2]); aB[3] = fmaf(w1, s1[7], aB[3]);
            e0 = n0; e1 = n1; p = pn;
        }
        #pragma unroll
        for (int j = 0; j < 4; j++) {
            aA[j] = redgrp(aA[j]);
            aB[j] = redgrp(aB[j]);
        }
        if (grp == 0) {
            float4 vA = make_float4(aA[0], aA[1], aA[2], aA[3]);
            float4 vB = make_float4(aB[0], aB[1], aB[2], aB[3]);
            *(float4*)(g_agg + n * HID + q)     = vA;
            *(float4*)(g_agg + n * HID + q + 4) = vB;
            lsA.x += vA.x; lsA.y += vA.y; lsA.z += vA.z; lsA.w += vA.w;
            lsB.x += vB.x; lsB.y += vB.y; lsB.z += vB.z; lsB.w += vB.w;
            lqA.x += vA.x * vA.x; lqA.y += vA.y * vA.y;
            lqA.z += vA.z * vA.z; lqA.w += vA.w * vA.w;
            lqB.x += vB.x * vB.x; lqB.y += vB.y * vB.y;
            lqB.z += vB.z * vB.z; lqB.w += vB.w * vB.w;
        }
    }
    if (grp == 0) {
        s_sA[wid][sub] = lsA; s_sB[wid][sub] = lsB;
        s_qA[wid][sub] = lqA; s_qB[wid][sub] = lqB;
    }
    __syncthreads();
    if (tid < 8) {
        float4 a = s_sA[0][tid], b = s_sB[0][tid];
        float4 c = s_qA[0][tid], d = s_qB[0][tid];
        #pragma unroll
        for (int wv = 1; wv < 8; wv++) {
            float4 t;
            t = s_sA[wv][tid]; a.x += t.x; a.y += t.y; a.z += t.z; a.w += t.w;
            t = s_sB[wv][tid]; b.x += t.x; b.y += t.y; b.z += t.z; b.w += t.w;
            t = s_qA[wv][tid]; c.x += t.x; c.y += t.y; c.z += t.z; c.w += t.w;
            t = s_qB[wv][tid]; d.x += t.x; d.y += t.y; d.z += t.z; d.w += t.w;
        }
        float* st = g_stats[wb];
        int base = tid * 8;
        atomicAdd(&st[base + 0], a.x); atomicAdd(&st[base + 1], a.y);
        atomicAdd(&st[base + 2], a.z); atomicAdd(&st[base + 3], a.w);
        atomicAdd(&st[base + 4], b.x); atomicAdd(&st[base + 5], b.y);
        atomicAdd(&st[base + 6], b.z); atomicAdd(&st[base + 7], b.w);
        atomicAdd(&st[HID + base + 0], c.x); atomicAdd(&st[HID + base + 1], c.y);
        atomicAdd(&st[HID + base + 2], c.z); atomicAdd(&st[HID + base + 3], c.w);
        atomicAdd(&st[HID + base + 4], d.x); atomicAdd(&st[HID + base + 5], d.y);
        atomicAdd(&st[HID + base + 6], d.z); atomicAdd(&st[HID + base + 7], d.w);
    }
}

// ---------------- output GEMM with fused final BN ------------------------------
__global__ __launch_bounds__(256) void k_outgemm(const float* __restrict__ Wo,
                                                 const float* __restrict__ bo,
                                                 const float* __restrict__ gamma,
                                                 const float* __restrict__ beta,
                                                 int rb,
                                                 float* __restrict__ out) {
    __shared__ float Ws[HID * OUTF];
    __shared__ float bs[OUTF];
    __shared__ float hp[32][HID];
    __shared__ float scs[HID];
    __shared__ float shs[HID];
    int tid = threadIdx.x;
    for (int i = tid; i < HID * OUTF; i += 256) Ws[i] = Wo[i];
    if (tid < OUTF) bs[tid] = bo[tid];
    if (tid < HID) {
        float m = g_stats[rb][tid] * (1.0f / Nn);
        float v = g_stats[rb][HID + tid] * (1.0f / Nn) - m * m;
        float inv = rsqrtf(v + EPSBN);
        float scale = gamma[tid] * inv;
        scs[tid] = scale;
        shs[tid] = beta[tid] - m * scale;
    }
    __syncthreads();
    int rowBase = blockIdx.x * 32;
    for (int i = tid; i < 32 * HID; i += 256) {
        int rr = i >> 6, f = i & 63;
        int gr = rowBase + rr;
        float hv = g_hprev[gr * HID + f]
                 + fmaxf(fmaf(g_agg[gr * HID + f], scs[f], shs[f]), 0.0f);
        hp[rr][f] = hv;
    }
    __syncthreads();
    for (int idx = tid; idx < 32 * OUTF; idx += 256) {
        int rr = idx / OUTF, f = idx % OUTF;
        int gr = rowBase + rr;
        float acc = bs[f];
        #pragma unroll
        for (int k = 0; k < HID; k++) acc += hp[rr][k] * Ws[k * OUTF + f];
        out[gr * OUTF + f] = acc;
    }
}

// ---------------- launch --------------------------------------------------------
extern "C" void kernel_launch(void* const* d_in, const int* in_sizes, int n_in,
                              void* d_out, int out_size) {
    const float* x     = (const float*)d_in[0];
    const void*  ei    = d_in[1];
    const float* Wi    = (const float*)d_in[2];
    const float* bi    = (const float*)d_in[3];
    const float* w1    = (const float*)d_in[4];
    const float* w2    = (const float*)d_in[5];
    const float* gamma = (const float*)d_in[6];
    const float* beta  = (const float*)d_in[7];
    const float* Wo    = (const float*)d_in[8];
    const float* bo    = (const float*)d_in[9];
    float* out = (float*)d_out;

    static cudaStream_t s1 = nullptr, s2 = nullptr;
    static cudaEvent_t ev0, evF, evCsr, evI, evDone;
    if (!s1) {
        cudaStreamCreateWithFlags(&s1, cudaStreamNonBlocking);
        cudaStreamCreateWithFlags(&s2, cudaStreamNonBlocking);
        cudaEventCreateWithFlags(&ev0,    cudaEventDisableTiming);
        cudaEventCreateWithFlags(&evF,    cudaEventDisableTiming);
        cudaEventCreateWithFlags(&evCsr,  cudaEventDisableTiming);
        cudaEventCreateWithFlags(&evI,    cudaEventDisableTiming);
        cudaEventCreateWithFlags(&evDone, cudaEventDisableTiming);
        cudaFuncSetAttribute(k_fused0, cudaFuncAttributeMaxDynamicSharedMemorySize,
                             FUSED_SMEM);
        cudaFuncSetAttribute(k_gemm_hp, cudaFuncAttributeMaxDynamicSharedMemorySize,
                             GEMM_SMEM);
        cudaFuncSetAttribute(k_gemm_init3, cudaFuncAttributeMaxDynamicSharedMemorySize,
                             GEMM_SMEM);
    }

    void* cnt_ptr = nullptr;
    void* stats_ptr = nullptr;
    cudaGetSymbolAddress(&cnt_ptr, g_cnt);
    cudaGetSymbolAddress(&stats_ptr, g_stats);
    float* initp = nullptr;
    cudaGetSymbolAddress((void**)&initp, g_init);
    const float* h0p = nullptr;
    cudaGetSymbolAddress((void**)&h0p, g_h0);
    const float* hpp = nullptr;
    cudaGetSymbolAddress((void**)&hpp, g_hprev);

    cudaMemsetAsync(cnt_ptr, 0, Nn * sizeof(int));
    cudaMemsetAsync(stats_ptr, 0, 4 * HID * sizeof(float));
    cudaEventRecord(ev0, 0);
    cudaStreamWaitEvent(s1, ev0, 0);
    cudaStreamWaitEvent(s2, ev0, 0);

    // s1: fused prologue (h0, supph0, init0)
    k_fused0<<<NTILE, 256, FUSED_SMEM, s1>>>(x, Wi, bi, w1, w2, initp);
    cudaEventRecord(evF, s1);

    // s2: CSR build, then init GEMMs for layers 1-3
    k_deg<<<(Ee + 255) / 256, 256, 0, s2>>>(ei);
    k_bsum<<<NB_SCAN, 256, 0, s2>>>();
    k_bscan<<<1, 512, 0, s2>>>();
    k_rowptr<<<NB_SCAN, 256, 0, s2>>>();
    k_fill<<<(Ee + 255) / 256, 256, 0, s2>>>(ei);
    cudaEventRecord(evCsr, s2);
    cudaStreamWaitEvent(s2, evF, 0);
    k_gemm_init3<<<3 * NTILE, 256, GEMM_SMEM, s2>>>(w2, initp);
    cudaEventRecord(evI, s2);

    // s1: layer chain
    cudaStreamWaitEvent(s1, evCsr, 0);
    k_gather<<<592, 256, 0, s1>>>(0, initp);
    for (int l = 1; l < NL; l++) {
        int wb = l & 1;
        int rb = (l - 1) & 1;
        const float* hs = (l == 1) ? h0p : hpp;
        k_gemm_hp<<<NTILE, 256, GEMM_SMEM, s1>>>(w1 + l * HID * HID,
                                                 gamma + (l - 1) * HID,
                                                 beta + (l - 1) * HID, hs, rb, wb);
        if (l == 1) cudaStreamWaitEvent(s1, evI, 0);
        k_gather<<<592, 256, 0, s1>>>(wb, initp + l * Nn * HID);
    }
    k_outgemm<<<Nn / 32, 256, 0, s1>>>(Wo, bo, gamma + (NL - 1) * HID,
                                       beta + (NL - 1) * HID, (NL - 1) & 1, out);

    cudaEventRecord(evDone, s1);
    cudaStreamWaitEvent(0, evDone, 0);
}